// round 10
// baseline (speedup 1.0000x reference)
#include <cuda_runtime.h>
#include <cuda_fp16.h>
#include <cstdint>

#define EPS 1e-5f

constexpr int B   = 4;
constexpr int H   = 8;
constexpr int SEQ = 4096;
constexpr int E   = 64;
constexpr int D   = 512;          // H*E
constexpr int BH  = B * H;        // 32
constexpr int L   = 64;           // chunk length
constexpr int C   = SEQ / L;      // 64 chunks per (b,h)
constexpr int M   = B * SEQ;      // 16384 GEMM rows
constexpr int NBLK = BH * C;      // 2048 scan blocks

// Task schedule: per group g: 32 attn tasks (chunk g) + 8 gemm tasks (chunk g-LAG)
constexpr int LAG     = 3;
constexpr int GPS     = 40;
constexpr int NGROUPS = C + LAG;          // 67
constexpr int NTASK   = NGROUPS * GPS;    // 2680

// Scratch (device globals — no allocation allowed)
__device__ __half g_Af[(size_t)M * D];
__device__ __half g_Wh[(size_t)D * D];
__device__ float g_aggk[NBLK * E];
__device__ float g_aggv[NBLK * E];
__device__ float g_inck[NBLK * E];
__device__ float g_incv[NBLK * E];
__device__ int   g_flag[NBLK];            // scan: 0=none,1=agg,2=inclusive
__device__ int   g_rowflag[B * C];        // #heads done for (b,c) row block
__device__ int   g_task;

__device__ __forceinline__ float phi(float x) {
    return x > 0.f ? x + 1.f : __expf(x);
}
__device__ __forceinline__ uint32_t smem_u32(const void* p) {
    uint32_t a;
    asm("{ .reg .u64 t; cvta.to.shared.u64 t, %1; cvt.u32.u64 %0, t; }"
        : "=r"(a) : "l"(p));
    return a;
}

// ---------------------------------------------------------------------------
// Init + W convert (one launch): reset flags/counters, W fp32->fp16.
// ---------------------------------------------------------------------------
__global__ __launch_bounds__(256) void init_wconv_kernel(const float* __restrict__ W)
{
    const int t = blockIdx.x * 256 + threadIdx.x;   // 0..65535
    if (t < NBLK)  g_flag[t] = 0;
    if (t < B * C) g_rowflag[t] = 0;
    if (t == 0)    g_task = 0;

    const int i = t * 4;
    float4 w = *(const float4*)(W + i);
    __half2 h01; h01.x = __float2half_rn(w.x); h01.y = __float2half_rn(w.y);
    __half2 h23; h23.x = __float2half_rn(w.z); h23.y = __float2half_rn(w.w);
    *(__half2*)(g_Wh + i)     = h01;
    *(__half2*)(g_Wh + i + 2) = h23;
}

// ============================ GEMM config ===================================
constexpr int BK     = 32;
constexpr int NK     = D / BK;        // 16
constexpr int NSTAGE = 4;
constexpr int RS     = 80;
constexpr int MTXA   = 64 * RS;       // 5120
constexpr int MTXB   = 256 * RS;      // 20480
constexpr int STG    = MTXA + MTXB;   // 25600
constexpr int DSMEM  = NSTAGE * STG;  // 102400 (attn overlays first ~35KB)

__device__ __forceinline__ void cp16(uint32_t dst, const void* src) {
    asm volatile("cp.async.cg.shared.global [%0], [%1], 16;"
                 :: "r"(dst), "l"(src) : "memory");
}
__device__ __forceinline__ void cp_commit() {
    asm volatile("cp.async.commit_group;" ::: "memory");
}
template<int N> __device__ __forceinline__ void cp_wait() {
    asm volatile("cp.async.wait_group %0;" :: "n"(N) : "memory");
}
__device__ __forceinline__ void ldsm4(uint32_t* r, uint32_t a) {
    asm volatile("ldmatrix.sync.aligned.m8n8.x4.shared.b16 {%0,%1,%2,%3}, [%4];"
                 : "=r"(r[0]), "=r"(r[1]), "=r"(r[2]), "=r"(r[3]) : "r"(a));
}
__device__ __forceinline__ void mma16816(float* c, const uint32_t* a,
                                         uint32_t b0, uint32_t b1) {
    asm volatile(
        "mma.sync.aligned.m16n8k16.row.col.f32.f16.f16.f32 "
        "{%0,%1,%2,%3}, {%4,%5,%6,%7}, {%8,%9}, {%0,%1,%2,%3};"
        : "+f"(c[0]), "+f"(c[1]), "+f"(c[2]), "+f"(c[3])
        : "r"(a[0]), "r"(a[1]), "r"(a[2]), "r"(a[3]), "r"(b0), "r"(b1));
}

// ---------------------------------------------------------------------------
// Attn task: one (bh, c) block. Decoupled lookback + in-chunk scan + ratio.
// ---------------------------------------------------------------------------
__device__ __forceinline__ void attn_task(
    int c, int bh, char* sm,
    const float* __restrict__ q, const float* __restrict__ k,
    const float* __restrict__ v)
{
    float* ks = (float*)sm;                         // 16 KB
    float* vs = (float*)(sm + 16384);               // 16 KB
    float (*shk)[64] = (float(*)[64])(sm + 32768);  // 1 KB
    float (*shv)[64] = (float(*)[64])(sm + 33792);  // 1 KB
    float* prefk = (float*)(sm + 34816);            // 256 B
    float* prefv = (float*)(sm + 35072);            // 256 B

    const int tid  = threadIdx.x;
    const int w    = tid >> 5;
    const int lane = tid & 31;
    const int e0   = lane * 2;
    const int blk  = bh * C + c;
    const int b    = bh / H;
    const int h    = bh % H;
    const size_t base = (size_t)blk * (L * E);

    // prefetch q rows for the dot phase
    float2 qreg[8];
    #pragma unroll
    for (int r = 0; r < 8; ++r)
        qreg[r] = *(const float2*)(q + base + (size_t)(w * 8 + r) * E + e0);

    // load k,v + feature map
    #pragma unroll
    for (int i = tid; i < (L * E) / 4; i += 256) {
        float4 kk = ((const float4*)(k + base))[i];
        kk.x = phi(kk.x); kk.y = phi(kk.y); kk.z = phi(kk.z); kk.w = phi(kk.w);
        ((float4*)ks)[i] = kk;
        ((float4*)vs)[i] = ((const float4*)(v + base))[i];
    }
    __syncthreads();

    // partial chunk aggregates
    {
        const int e = tid & 63, g = tid >> 6;
        float sk = 0.f, sv = 0.f;
        #pragma unroll 4
        for (int r = g * 16; r < g * 16 + 16; ++r) {
            sk += ks[r * E + e];
            sv += vs[r * E + e];
        }
        shk[g][e] = sk; shv[g][e] = sv;
    }
    __syncthreads();

    if (tid < 64) {
        g_aggk[blk * E + tid] = shk[0][tid] + shk[1][tid] + shk[2][tid] + shk[3][tid];
    } else if (tid < 128) {
        const int e = tid - 64;
        g_aggv[blk * E + e] = shv[0][e] + shv[1][e] + shv[2][e] + shv[3][e];
    }
    __threadfence();
    __syncthreads();
    if (tid == 0) atomicExch(&g_flag[blk], 1);

    // warp-0-only decoupled lookback
    if (w == 0) {
        float aK0 = 0.f, aK1 = 0.f, aV0 = 0.f, aV1 = 0.f;
        for (int p = c - 1; p >= 0; --p) {
            const int pblk = bh * C + p;
            int f = 0;
            if (lane == 0) {
                do { f = atomicAdd(&g_flag[pblk], 0); } while (f == 0);
            }
            f = __shfl_sync(0xffffffffu, f, 0);
            __threadfence();
            const float* srcK = (f == 2) ? g_inck : g_aggk;
            const float* srcV = (f == 2) ? g_incv : g_aggv;
            aK0 += srcK[pblk * E + lane];
            aK1 += srcK[pblk * E + lane + 32];
            aV0 += srcV[pblk * E + lane];
            aV1 += srcV[pblk * E + lane + 32];
            if (f == 2) break;
        }
        const float gK0 = shk[0][lane] + shk[1][lane] + shk[2][lane] + shk[3][lane];
        const float gK1 = shk[0][lane+32] + shk[1][lane+32] + shk[2][lane+32] + shk[3][lane+32];
        const float gV0 = shv[0][lane] + shv[1][lane] + shv[2][lane] + shv[3][lane];
        const float gV1 = shv[0][lane+32] + shv[1][lane+32] + shv[2][lane+32] + shv[3][lane+32];
        g_inck[blk * E + lane]      = aK0 + gK0;
        g_inck[blk * E + lane + 32] = aK1 + gK1;
        g_incv[blk * E + lane]      = aV0 + gV0;
        g_incv[blk * E + lane + 32] = aV1 + gV1;
        __threadfence();
        if (lane == 0) atomicExch(&g_flag[blk], 2);
        prefk[lane]      = aK0;  prefk[lane + 32] = aK1;
        prefv[lane]      = aV0;  prefv[lane + 32] = aV1;
    }
    __syncthreads();

    // in-chunk serial scans
    if (tid < 64) {
        float ak = prefk[tid];
        #pragma unroll 8
        for (int i = 0; i < L; ++i) { ak += ks[i * E + tid]; ks[i * E + tid] = ak; }
    } else if (tid < 128) {
        const int e = tid - 64;
        float av = prefv[e];
        #pragma unroll 8
        for (int i = 0; i < L; ++i) { av += vs[i * E + e]; vs[i * E + e] = av; }
    }
    __syncthreads();

    // per-row dot + ratio + fp16 write
    const int n0 = c * L;
    #pragma unroll
    for (int r = 0; r < 8; ++r) {
        const int i = w * 8 + r;
        float p = phi(qreg[r].x) * ks[i * E + e0] + phi(qreg[r].y) * ks[i * E + e0 + 1];
        #pragma unroll
        for (int off = 16; off; off >>= 1)
            p += __shfl_xor_sync(0xffffffffu, p, off);
        float ratio = p / (p + EPS);
        size_t ob = ((size_t)b * SEQ + n0 + i) * D + (size_t)h * E + e0;
        float2 x = { ratio * vs[i * E + e0], ratio * vs[i * E + e0 + 1] };
        *(__half2*)(g_Af + ob) = __float22half2_rn(x);
    }

    // publish this (b,c) head-slice completion
    __threadfence();
    __syncthreads();
    if (tid == 0) atomicAdd(&g_rowflag[b * C + c], 1);
}

// ---------------------------------------------------------------------------
// GEMM task: tile bm = b*64+c (64 rows), bn half of N. Waits for 8 heads.
// ---------------------------------------------------------------------------
__device__ __forceinline__ void gemm_task(
    int c, int j, char* sm,
    const float* __restrict__ bias, float* __restrict__ out)
{
    const int tid  = threadIdx.x;
    const int lane = tid & 31;
    const int wid  = tid >> 5;
    const int wm   = wid & 1;
    const int wn   = wid >> 1;
    const int b    = j >> 1;
    const int bn   = j & 1;
    const int bm   = b * 64 + c;
    const uint32_t sbase = smem_u32(sm);

    // wait for all 8 attn head-blocks of (b,c)
    if (tid == 0) {
        while (atomicAdd(&g_rowflag[b * C + c], 0) < H) { }
    }
    __syncthreads();
    __threadfence();   // order subsequent reads after observed flag

    auto load_stage = [&](int s, int kt) {
        const int k0 = kt * BK;
        const uint32_t d0 = sbase + s * STG;
        {
            const int r = tid >> 2, cc = tid & 3;
            const uint32_t so = (uint32_t)(r * RS + cc * 16);
            cp16(d0 + so, g_Af + (size_t)(bm * 64 + r) * D + k0 + cc * 8);
        }
        #pragma unroll
        for (int hh = 0; hh < 4; ++hh) {
            const int jj = tid + hh * 256;
            const int r = jj >> 2, cc = jj & 3;
            const uint32_t so = (uint32_t)(r * RS + cc * 16);
            cp16(d0 + MTXA + so, g_Wh + (size_t)(bn * 256 + r) * D + k0 + cc * 8);
        }
    };

    const int lrow = lane & 15, lkh = lane >> 4;
    const uint32_t aoff = (uint32_t)((wm * 32 + lrow) * RS + lkh * 16);
    const uint32_t boff = (uint32_t)(MTXA + (wn * 64 + lrow) * RS + lkh * 16);

    float acc[2][8][4] = {};

    #pragma unroll
    for (int p = 0; p < NSTAGE - 1; ++p) { load_stage(p, p); cp_commit(); }

    for (int kt = 0; kt < NK; ++kt) {
        cp_wait<NSTAGE - 2>();
        __syncthreads();

        const uint32_t st0 = sbase + (kt & (NSTAGE - 1)) * STG;
        #pragma unroll
        for (int st = 0; st < 2; ++st) {
            uint32_t af[2][4], bf[4][4];
            #pragma unroll
            for (int mi = 0; mi < 2; ++mi)
                ldsm4(af[mi], st0 + aoff + mi * (16 * RS) + st * 32);
            #pragma unroll
            for (int nt = 0; nt < 4; ++nt)
                ldsm4(bf[nt], st0 + boff + nt * (16 * RS) + st * 32);
            #pragma unroll
            for (int mi = 0; mi < 2; ++mi)
                #pragma unroll
                for (int nt = 0; nt < 4; ++nt) {
                    mma16816(acc[mi][nt*2+0], af[mi], bf[nt][0], bf[nt][2]);
                    mma16816(acc[mi][nt*2+1], af[mi], bf[nt][1], bf[nt][3]);
                }
        }

        if (kt + NSTAGE - 1 < NK)
            load_stage((kt + NSTAGE - 1) & (NSTAGE - 1), kt + NSTAGE - 1);
        cp_commit();
    }
    cp_wait<0>();   // drain (empty) groups before smem reuse by next task

    const int g   = lane >> 2;
    const int tig = lane & 3;
    #pragma unroll
    for (int mi = 0; mi < 2; ++mi) {
        const int row0 = bm * 64 + wm * 32 + mi * 16 + g;
        #pragma unroll
        for (int nt = 0; nt < 4; ++nt)
            #pragma unroll
            for (int nh = 0; nh < 2; ++nh) {
                const float* a4 = acc[mi][nt * 2 + nh];
                const int col = bn * 256 + wn * 64 + nt * 16 + nh * 8 + tig * 2;
                const float2 bv = *(const float2*)(bias + col);
                float2 o0 = { a4[0] + bv.x, a4[1] + bv.y };
                float2 o1 = { a4[2] + bv.x, a4[3] + bv.y };
                *(float2*)(out + (size_t)row0 * D + col)       = o0;
                *(float2*)(out + (size_t)(row0 + 8) * D + col) = o1;
            }
    }
}

// ---------------------------------------------------------------------------
// Persistent mega-kernel: claims tasks off a global counter.
// Group g: tasks 0..31 -> attn(chunk g, bh); 32..39 -> gemm(chunk g-LAG).
// Claim order guarantees deps claimed (thus scheduled) earlier: deadlock-free.
// ---------------------------------------------------------------------------
__global__ __launch_bounds__(256, 2) void mega_kernel(
    const float* __restrict__ q, const float* __restrict__ k,
    const float* __restrict__ v, const float* __restrict__ bias,
    float* __restrict__ out)
{
    extern __shared__ char sm[];
    __shared__ int s_task;
    const int tid = threadIdx.x;

    for (;;) {
        __syncthreads();                 // protect s_task + smem reuse
        if (tid == 0) s_task = atomicAdd(&g_task, 1);
        __syncthreads();
        const int t = s_task;
        if (t >= NTASK) return;
        const int g = t / GPS;
        const int r = t % GPS;
        if (r < 32) {
            if (g < C) attn_task(g, r, sm, q, k, v);
        } else {
            const int c = g - LAG;
            if (c >= 0 && c < C) gemm_task(c, r - 32, sm, bias, out);
        }
    }
}

// ---------------------------------------------------------------------------
extern "C" void kernel_launch(void* const* d_in, const int* in_sizes, int n_in,
                              void* d_out, int out_size)
{
    const float* q    = (const float*)d_in[0];
    const float* k    = (const float*)d_in[1];
    const float* v    = (const float*)d_in[2];
    // d_in[3] = mask (unused)
    const float* W    = (const float*)d_in[4];
    const float* bias = (const float*)d_in[5];
    float* out = (float*)d_out;

    cudaFuncSetAttribute(mega_kernel,
                         cudaFuncAttributeMaxDynamicSharedMemorySize, DSMEM);

    init_wconv_kernel<<<(D * D) / 1024, 256>>>(W);
    mega_kernel<<<304, 256, DSMEM>>>(q, k, v, bias, out);
}

// round 11
// speedup vs baseline: 1.2765x; 1.2765x over previous
#include <cuda_runtime.h>
#include <cuda_fp16.h>
#include <cstdint>

#define EPS 1e-5f

constexpr int B   = 4;
constexpr int H   = 8;
constexpr int SEQ = 4096;
constexpr int E   = 64;
constexpr int D   = 512;          // H*E
constexpr int BH  = B * H;        // 32
constexpr int L   = 64;           // chunk length
constexpr int C   = SEQ / L;      // 64 chunks per (b,h)
constexpr int M   = B * SEQ;      // 16384 GEMM rows
constexpr int NBLK = BH * C;      // 2048 scan blocks

// Task schedule: group g = 32 attn (chunk g) + 16 gemm (chunk g-LAG, j=b*4+bn)
constexpr int LAG     = 4;
constexpr int GPS     = 48;
constexpr int NGROUPS = C + LAG;          // 68
constexpr int NTASK   = NGROUPS * GPS;    // 3264

// Scratch (device globals — no allocation allowed)
__device__ __half g_Af[(size_t)M * D];
__device__ __half g_Wh[(size_t)D * D];
__device__ float g_aggk[NBLK * E];
__device__ float g_aggv[NBLK * E];
__device__ float g_inck[NBLK * E];
__device__ float g_incv[NBLK * E];
__device__ int   g_flag[NBLK];            // scan: 0=none,1=agg,2=inclusive
__device__ int   g_rowflag[B * C];        // #heads done for (b,c) row block
__device__ int   g_task;

__device__ __forceinline__ float phi(float x) {
    return x > 0.f ? x + 1.f : __expf(x);
}
__device__ __forceinline__ uint32_t smem_u32(const void* p) {
    uint32_t a;
    asm("{ .reg .u64 t; cvta.to.shared.u64 t, %1; cvt.u32.u64 %0, t; }"
        : "=r"(a) : "l"(p));
    return a;
}

// ---------------------------------------------------------------------------
// Init + W convert (one launch): reset flags/counters, W fp32->fp16.
// ---------------------------------------------------------------------------
__global__ __launch_bounds__(256) void init_wconv_kernel(const float* __restrict__ W)
{
    const int t = blockIdx.x * 256 + threadIdx.x;   // 0..65535
    if (t < NBLK)  g_flag[t] = 0;
    if (t < B * C) g_rowflag[t] = 0;
    if (t == 0)    g_task = 0;

    const int i = t * 4;
    float4 w = *(const float4*)(W + i);
    __half2 h01; h01.x = __float2half_rn(w.x); h01.y = __float2half_rn(w.y);
    __half2 h23; h23.x = __float2half_rn(w.z); h23.y = __float2half_rn(w.w);
    *(__half2*)(g_Wh + i)     = h01;
    *(__half2*)(g_Wh + i + 2) = h23;
}

// ============================ GEMM config (small tile) ======================
constexpr int BK     = 32;
constexpr int NK     = D / BK;        // 16
constexpr int NSTAGE = 3;
constexpr int RS     = 80;
constexpr int MTXA   = 64 * RS;       // 5120  (A: 64 rows)
constexpr int MTXB   = 128 * RS;      // 10240 (W: 128 rows)
constexpr int STG    = MTXA + MTXB;   // 15360
constexpr int DSMEM  = NSTAGE * STG;  // 46080 (attn overlays 35328 of it)

__device__ __forceinline__ void cp16(uint32_t dst, const void* src) {
    asm volatile("cp.async.cg.shared.global [%0], [%1], 16;"
                 :: "r"(dst), "l"(src) : "memory");
}
__device__ __forceinline__ void cp_commit() {
    asm volatile("cp.async.commit_group;" ::: "memory");
}
template<int N> __device__ __forceinline__ void cp_wait() {
    asm volatile("cp.async.wait_group %0;" :: "n"(N) : "memory");
}
__device__ __forceinline__ void ldsm4(uint32_t* r, uint32_t a) {
    asm volatile("ldmatrix.sync.aligned.m8n8.x4.shared.b16 {%0,%1,%2,%3}, [%4];"
                 : "=r"(r[0]), "=r"(r[1]), "=r"(r[2]), "=r"(r[3]) : "r"(a));
}
__device__ __forceinline__ void mma16816(float* c, const uint32_t* a,
                                         uint32_t b0, uint32_t b1) {
    asm volatile(
        "mma.sync.aligned.m16n8k16.row.col.f32.f16.f16.f32 "
        "{%0,%1,%2,%3}, {%4,%5,%6,%7}, {%8,%9}, {%0,%1,%2,%3};"
        : "+f"(c[0]), "+f"(c[1]), "+f"(c[2]), "+f"(c[3])
        : "r"(a[0]), "r"(a[1]), "r"(a[2]), "r"(a[3]), "r"(b0), "r"(b1));
}

// ---------------------------------------------------------------------------
// Attn task: one (bh, c) block. Decoupled lookback + in-chunk scan + ratio.
// ---------------------------------------------------------------------------
__device__ __forceinline__ void attn_task(
    int c, int bh, char* sm,
    const float* __restrict__ q, const float* __restrict__ k,
    const float* __restrict__ v)
{
    float* ks = (float*)sm;                         // 16 KB
    float* vs = (float*)(sm + 16384);               // 16 KB
    float (*shk)[64] = (float(*)[64])(sm + 32768);  // 1 KB
    float (*shv)[64] = (float(*)[64])(sm + 33792);  // 1 KB
    float* prefk = (float*)(sm + 34816);            // 256 B
    float* prefv = (float*)(sm + 35072);            // 256 B

    const int tid  = threadIdx.x;
    const int w    = tid >> 5;
    const int lane = tid & 31;
    const int e0   = lane * 2;
    const int blk  = bh * C + c;
    const int b    = bh / H;
    const int h    = bh % H;
    const size_t base = (size_t)blk * (L * E);

    float2 qreg[8];
    #pragma unroll
    for (int r = 0; r < 8; ++r)
        qreg[r] = *(const float2*)(q + base + (size_t)(w * 8 + r) * E + e0);

    #pragma unroll
    for (int i = tid; i < (L * E) / 4; i += 256) {
        float4 kk = ((const float4*)(k + base))[i];
        kk.x = phi(kk.x); kk.y = phi(kk.y); kk.z = phi(kk.z); kk.w = phi(kk.w);
        ((float4*)ks)[i] = kk;
        ((float4*)vs)[i] = ((const float4*)(v + base))[i];
    }
    __syncthreads();

    {
        const int e = tid & 63, g = tid >> 6;
        float sk = 0.f, sv = 0.f;
        #pragma unroll 4
        for (int r = g * 16; r < g * 16 + 16; ++r) {
            sk += ks[r * E + e];
            sv += vs[r * E + e];
        }
        shk[g][e] = sk; shv[g][e] = sv;
    }
    __syncthreads();

    if (tid < 64) {
        g_aggk[blk * E + tid] = shk[0][tid] + shk[1][tid] + shk[2][tid] + shk[3][tid];
    } else if (tid < 128) {
        const int e = tid - 64;
        g_aggv[blk * E + e] = shv[0][e] + shv[1][e] + shv[2][e] + shv[3][e];
    }
    __threadfence();
    __syncthreads();
    if (tid == 0) atomicExch(&g_flag[blk], 1);

    if (w == 0) {
        float aK0 = 0.f, aK1 = 0.f, aV0 = 0.f, aV1 = 0.f;
        for (int p = c - 1; p >= 0; --p) {
            const int pblk = bh * C + p;
            int f = 0;
            if (lane == 0) {
                do { f = atomicAdd(&g_flag[pblk], 0); } while (f == 0);
            }
            f = __shfl_sync(0xffffffffu, f, 0);
            __threadfence();
            const float* srcK = (f == 2) ? g_inck : g_aggk;
            const float* srcV = (f == 2) ? g_incv : g_aggv;
            aK0 += srcK[pblk * E + lane];
            aK1 += srcK[pblk * E + lane + 32];
            aV0 += srcV[pblk * E + lane];
            aV1 += srcV[pblk * E + lane + 32];
            if (f == 2) break;
        }
        const float gK0 = shk[0][lane] + shk[1][lane] + shk[2][lane] + shk[3][lane];
        const float gK1 = shk[0][lane+32] + shk[1][lane+32] + shk[2][lane+32] + shk[3][lane+32];
        const float gV0 = shv[0][lane] + shv[1][lane] + shv[2][lane] + shv[3][lane];
        const float gV1 = shv[0][lane+32] + shv[1][lane+32] + shv[2][lane+32] + shv[3][lane+32];
        g_inck[blk * E + lane]      = aK0 + gK0;
        g_inck[blk * E + lane + 32] = aK1 + gK1;
        g_incv[blk * E + lane]      = aV0 + gV0;
        g_incv[blk * E + lane + 32] = aV1 + gV1;
        __threadfence();
        if (lane == 0) atomicExch(&g_flag[blk], 2);
        prefk[lane]      = aK0;  prefk[lane + 32] = aK1;
        prefv[lane]      = aV0;  prefv[lane + 32] = aV1;
    }
    __syncthreads();

    if (tid < 64) {
        float ak = prefk[tid];
        #pragma unroll 8
        for (int i = 0; i < L; ++i) { ak += ks[i * E + tid]; ks[i * E + tid] = ak; }
    } else if (tid < 128) {
        const int e = tid - 64;
        float av = prefv[e];
        #pragma unroll 8
        for (int i = 0; i < L; ++i) { av += vs[i * E + e]; vs[i * E + e] = av; }
    }
    __syncthreads();

    const int n0 = c * L;
    #pragma unroll
    for (int r = 0; r < 8; ++r) {
        const int i = w * 8 + r;
        float p = phi(qreg[r].x) * ks[i * E + e0] + phi(qreg[r].y) * ks[i * E + e0 + 1];
        #pragma unroll
        for (int off = 16; off; off >>= 1)
            p += __shfl_xor_sync(0xffffffffu, p, off);
        float ratio = p / (p + EPS);
        size_t ob = ((size_t)b * SEQ + n0 + i) * D + (size_t)h * E + e0;
        float2 x = { ratio * vs[i * E + e0], ratio * vs[i * E + e0 + 1] };
        *(__half2*)(g_Af + ob) = __float22half2_rn(x);
    }

    __threadfence();
    __syncthreads();
    if (tid == 0) atomicAdd(&g_rowflag[b * C + c], 1);
}

// ---------------------------------------------------------------------------
// GEMM task: rows = (b,c) 64-row block, cols = bn*128. Warp tile 32x32.
// Low-footprint: 8 warps (2m x 4n), acc[2][4][4], NSTAGE=3, <=64 regs.
// ---------------------------------------------------------------------------
__device__ __forceinline__ void gemm_task(
    int c, int j, char* sm,
    const float* __restrict__ bias, float* __restrict__ out)
{
    const int tid  = threadIdx.x;
    const int lane = tid & 31;
    const int wid  = tid >> 5;
    const int wm   = wid & 1;       // 0..1: 32-row slab
    const int wn   = wid >> 1;      // 0..3: 32-col slab
    const int b    = j >> 2;
    const int bn   = j & 3;
    const int bm   = b * 64 + c;
    const uint32_t sbase = smem_u32(sm);

    if (tid == 0) {
        while (atomicAdd(&g_rowflag[b * C + c], 0) < H) { }
    }
    __syncthreads();
    __threadfence();

    auto load_stage = [&](int s, int kt) {
        const int k0 = kt * BK;
        const uint32_t d0 = sbase + s * STG;
        {   // A: 64 rows x 32 cols fp16 = 256 chunks, 1/thread
            const int r = tid >> 2, cc = tid & 3;
            cp16(d0 + (uint32_t)(r * RS + cc * 16),
                 g_Af + (size_t)(bm * 64 + r) * D + k0 + cc * 8);
        }
        #pragma unroll
        for (int hh = 0; hh < 2; ++hh) {   // W: 128 rows, 512 chunks, 2/thread
            const int jj = tid + hh * 256;
            const int r = jj >> 2, cc = jj & 3;
            cp16(d0 + MTXA + (uint32_t)(r * RS + cc * 16),
                 g_Wh + (size_t)(bn * 128 + r) * D + k0 + cc * 8);
        }
    };

    const int lrow = lane & 15, lkh = lane >> 4;
    const uint32_t aoff = (uint32_t)((wm * 32 + lrow) * RS + lkh * 16);
    const uint32_t boff = (uint32_t)(MTXA + (wn * 32 + lrow) * RS + lkh * 16);

    float acc[2][4][4] = {};

    #pragma unroll
    for (int p = 0; p < NSTAGE - 1; ++p) { load_stage(p, p); cp_commit(); }

    for (int kt = 0; kt < NK; ++kt) {
        cp_wait<NSTAGE - 2>();
        __syncthreads();

        const uint32_t st0 = sbase + (kt % NSTAGE) * STG;
        #pragma unroll
        for (int st = 0; st < 2; ++st) {
            uint32_t af[2][4], bf[2][4];
            #pragma unroll
            for (int mi = 0; mi < 2; ++mi)
                ldsm4(af[mi], st0 + aoff + mi * (16 * RS) + st * 32);
            #pragma unroll
            for (int nt = 0; nt < 2; ++nt)
                ldsm4(bf[nt], st0 + boff + nt * (16 * RS) + st * 32);
            #pragma unroll
            for (int mi = 0; mi < 2; ++mi)
                #pragma unroll
                for (int nt = 0; nt < 2; ++nt) {
                    mma16816(acc[mi][nt*2+0], af[mi], bf[nt][0], bf[nt][2]);
                    mma16816(acc[mi][nt*2+1], af[mi], bf[nt][1], bf[nt][3]);
                }
        }

        if (kt + NSTAGE - 1 < NK)
            load_stage((kt + NSTAGE - 1) % NSTAGE, kt + NSTAGE - 1);
        cp_commit();
    }
    cp_wait<0>();   // drain before smem reuse by next task

    const int g   = lane >> 2;
    const int tig = lane & 3;
    #pragma unroll
    for (int mi = 0; mi < 2; ++mi) {
        const int row0 = bm * 64 + wm * 32 + mi * 16 + g;
        #pragma unroll
        for (int nt = 0; nt < 2; ++nt)
            #pragma unroll
            for (int nh = 0; nh < 2; ++nh) {
                const float* a4 = acc[mi][nt * 2 + nh];
                const int col = bn * 128 + wn * 32 + nt * 16 + nh * 8 + tig * 2;
                const float2 bv = *(const float2*)(bias + col);
                float2 o0 = { a4[0] + bv.x, a4[1] + bv.y };
                float2 o1 = { a4[2] + bv.x, a4[3] + bv.y };
                *(float2*)(out + (size_t)row0 * D + col)       = o0;
                *(float2*)(out + (size_t)(row0 + 8) * D + col) = o1;
            }
    }
}

// ---------------------------------------------------------------------------
// Persistent mega-kernel, 4 CTAs/SM. Claim order = execution order =>
// every wait targets a smaller vid (already executing) => deadlock-free.
// ---------------------------------------------------------------------------
__global__ __launch_bounds__(256, 4) void mega_kernel(
    const float* __restrict__ q, const float* __restrict__ k,
    const float* __restrict__ v, const float* __restrict__ bias,
    float* __restrict__ out)
{
    extern __shared__ char sm[];
    __shared__ int s_task;
    const int tid = threadIdx.x;

    for (;;) {
        __syncthreads();                 // protect s_task + smem reuse
        if (tid == 0) s_task = atomicAdd(&g_task, 1);
        __syncthreads();
        const int t = s_task;
        if (t >= NTASK) return;
        const int g = t / GPS;
        const int r = t % GPS;
        if (r < 32) {
            if (g < C) attn_task(g, r, sm, q, k, v);
        } else {
            const int c = g - LAG;
            if (c >= 0) gemm_task(c, r - 32, sm, bias, out);
        }
    }
}

// ---------------------------------------------------------------------------
extern "C" void kernel_launch(void* const* d_in, const int* in_sizes, int n_in,
                              void* d_out, int out_size)
{
    const float* q    = (const float*)d_in[0];
    const float* k    = (const float*)d_in[1];
    const float* v    = (const float*)d_in[2];
    // d_in[3] = mask (unused)
    const float* W    = (const float*)d_in[4];
    const float* bias = (const float*)d_in[5];
    float* out = (float*)d_out;

    cudaFuncSetAttribute(mega_kernel,
                         cudaFuncAttributeMaxDynamicSharedMemorySize, DSMEM);

    init_wconv_kernel<<<(D * D) / 1024, 256>>>(W);
    mega_kernel<<<592, 256, DSMEM>>>(q, k, v, bias, out);
}

// round 12
// speedup vs baseline: 1.7383x; 1.3617x over previous
#include <cuda_runtime.h>
#include <cuda_fp16.h>
#include <cstdint>

#define EPS 1e-5f

constexpr int B   = 4;
constexpr int H   = 8;
constexpr int SEQ = 4096;
constexpr int E   = 64;
constexpr int D   = 512;          // H*E
constexpr int BH  = B * H;        // 32
constexpr int L   = 64;           // chunk length
constexpr int C   = SEQ / L;      // 64 chunks per (b,h)
constexpr int M   = B * SEQ;      // 16384 GEMM rows
constexpr int NBLK = BH * C;      // 2048 scan blocks

// Scratch (device globals — no allocation allowed)
__device__ __half g_Af[(size_t)M * D];     // A in fp16
__device__ __half g_Wh[(size_t)D * D];     // W in fp16
__device__ float g_aggk[NBLK * E];
__device__ float g_aggv[NBLK * E];
__device__ float g_inck[NBLK * E];
__device__ float g_incv[NBLK * E];
__device__ int   g_flag[NBLK];             // 0=none, 1=aggregate, 2=inclusive
__device__ int   g_vid_counter;

__device__ __forceinline__ float phi(float x) {
    return x > 0.f ? x + 1.f : __expf(x);
}
__device__ __forceinline__ uint32_t smem_u32(const void* p) {
    uint32_t a;
    asm("{ .reg .u64 t; cvta.to.shared.u64 t, %1; cvt.u32.u64 %0, t; }"
        : "=r"(a) : "l"(p));
    return a;
}

// ---------------------------------------------------------------------------
// Init + W convert (one launch): reset flags/counter, W fp32->fp16.
// ---------------------------------------------------------------------------
__global__ __launch_bounds__(256) void init_wconv_kernel(const float* __restrict__ W)
{
    const int t = blockIdx.x * 256 + threadIdx.x;   // 0..65535
    if (t < NBLK) g_flag[t] = 0;
    if (t == 0)   g_vid_counter = 0;

    const int i = t * 4;
    float4 w = *(const float4*)(W + i);
    __half2 h01; h01.x = __float2half_rn(w.x); h01.y = __float2half_rn(w.y);
    __half2 h23; h23.x = __float2half_rn(w.z); h23.y = __float2half_rn(w.w);
    *(__half2*)(g_Wh + i)     = h01;
    *(__half2*)(g_Wh + i + 2) = h23;
}

// ---------------------------------------------------------------------------
// Fused single-pass scan + attention (decoupled lookback).  (R9 version)
// ---------------------------------------------------------------------------
__global__ __launch_bounds__(256) void fused_attn_kernel(
    const float* __restrict__ q, const float* __restrict__ k,
    const float* __restrict__ v)
{
    __shared__ float ks[L * E];        // 16 KB
    __shared__ float vs[L * E];        // 16 KB
    __shared__ float shk[4][64], shv[4][64];
    __shared__ float prefk[64], prefv[64];
    __shared__ int   s_vid;

    const int tid  = threadIdx.x;
    const int w    = tid >> 5;
    const int lane = tid & 31;
    const int e0   = lane * 2;

    if (tid == 0) s_vid = atomicAdd(&g_vid_counter, 1);
    __syncthreads();
    const int vid = s_vid;
    const int c   = vid / BH;          // c-major: all 32 bh chains advance together
    const int bh  = vid % BH;
    const int blk = bh * C + c;
    const int b   = bh / H;
    const int h   = bh % H;
    const size_t base = (size_t)blk * (L * E);

    float2 qreg[8];
    #pragma unroll
    for (int r = 0; r < 8; ++r)
        qreg[r] = *(const float2*)(q + base + (size_t)(w * 8 + r) * E + e0);

    #pragma unroll
    for (int i = tid; i < (L * E) / 4; i += 256) {
        float4 kk = ((const float4*)(k + base))[i];
        kk.x = phi(kk.x); kk.y = phi(kk.y); kk.z = phi(kk.z); kk.w = phi(kk.w);
        ((float4*)ks)[i] = kk;
        ((float4*)vs)[i] = ((const float4*)(v + base))[i];
    }
    __syncthreads();

    {
        const int e = tid & 63, g = tid >> 6;
        float sk = 0.f, sv = 0.f;
        #pragma unroll 4
        for (int r = g * 16; r < g * 16 + 16; ++r) {
            sk += ks[r * E + e];
            sv += vs[r * E + e];
        }
        shk[g][e] = sk; shv[g][e] = sv;
    }
    __syncthreads();

    if (tid < 64) {
        g_aggk[blk * E + tid] = shk[0][tid] + shk[1][tid] + shk[2][tid] + shk[3][tid];
    } else if (tid < 128) {
        const int e = tid - 64;
        g_aggv[blk * E + e] = shv[0][e] + shv[1][e] + shv[2][e] + shv[3][e];
    }
    __threadfence();
    __syncthreads();
    if (tid == 0) atomicExch(&g_flag[blk], 1);

    if (w == 0) {
        float aK0 = 0.f, aK1 = 0.f, aV0 = 0.f, aV1 = 0.f;
        for (int p = c - 1; p >= 0; --p) {
            const int pblk = bh * C + p;
            int f = 0;
            if (lane == 0) {
                do { f = atomicAdd(&g_flag[pblk], 0); } while (f == 0);
            }
            f = __shfl_sync(0xffffffffu, f, 0);
            __threadfence();
            const float* srcK = (f == 2) ? g_inck : g_aggk;
            const float* srcV = (f == 2) ? g_incv : g_aggv;
            aK0 += srcK[pblk * E + lane];
            aK1 += srcK[pblk * E + lane + 32];
            aV0 += srcV[pblk * E + lane];
            aV1 += srcV[pblk * E + lane + 32];
            if (f == 2) break;
        }
        const float gK0 = shk[0][lane] + shk[1][lane] + shk[2][lane] + shk[3][lane];
        const float gK1 = shk[0][lane+32] + shk[1][lane+32] + shk[2][lane+32] + shk[3][lane+32];
        const float gV0 = shv[0][lane] + shv[1][lane] + shv[2][lane] + shv[3][lane];
        const float gV1 = shv[0][lane+32] + shv[1][lane+32] + shv[2][lane+32] + shv[3][lane+32];
        g_inck[blk * E + lane]      = aK0 + gK0;
        g_inck[blk * E + lane + 32] = aK1 + gK1;
        g_incv[blk * E + lane]      = aV0 + gV0;
        g_incv[blk * E + lane + 32] = aV1 + gV1;
        __threadfence();
        if (lane == 0) atomicExch(&g_flag[blk], 2);
        prefk[lane]      = aK0;  prefk[lane + 32] = aK1;
        prefv[lane]      = aV0;  prefv[lane + 32] = aV1;
    }
    __syncthreads();

    if (tid < 64) {
        float ak = prefk[tid];
        #pragma unroll 8
        for (int i = 0; i < L; ++i) { ak += ks[i * E + tid]; ks[i * E + tid] = ak; }
    } else if (tid < 128) {
        const int e = tid - 64;
        float av = prefv[e];
        #pragma unroll 8
        for (int i = 0; i < L; ++i) { av += vs[i * E + e]; vs[i * E + e] = av; }
    }
    __syncthreads();

    const int n0 = c * L;
    #pragma unroll
    for (int r = 0; r < 8; ++r) {
        const int i = w * 8 + r;
        float p = phi(qreg[r].x) * ks[i * E + e0] + phi(qreg[r].y) * ks[i * E + e0 + 1];
        #pragma unroll
        for (int off = 16; off; off >>= 1)
            p += __shfl_xor_sync(0xffffffffu, p, off);
        float ratio = p / (p + EPS);
        size_t ob = ((size_t)b * SEQ + n0 + i) * D + (size_t)h * E + e0;
        float2 x = { ratio * vs[i * E + e0], ratio * vs[i * E + e0 + 1] };
        *(__half2*)(g_Af + ob) = __float22half2_rn(x);
    }
}

// ---------------------------------------------------------------------------
// GEMM: out[M,512] = A @ W^T + bias, fp16 MMA, fp32 accum.
// Small tile for occupancy: BM=64, BN=128, BK=32, 8 warps (2m x 4n),
// warp tile 32x32, NSTAGE=3, <=64 regs -> 4 CTAs/SM (8 warps/SMSP).
// W is [n][k] row-major -> NON-trans ldmatrix for B.
// ---------------------------------------------------------------------------
constexpr int BK     = 32;
constexpr int NK     = D / BK;        // 16
constexpr int NSTAGE = 3;
constexpr int RS     = 80;
constexpr int MTXA   = 64 * RS;       // 5120
constexpr int MTXB   = 128 * RS;      // 10240
constexpr int STG    = MTXA + MTXB;   // 15360
constexpr int GEMM_DSMEM = NSTAGE * STG;  // 46080

__device__ __forceinline__ void cp16(uint32_t dst, const void* src) {
    asm volatile("cp.async.cg.shared.global [%0], [%1], 16;"
                 :: "r"(dst), "l"(src) : "memory");
}
__device__ __forceinline__ void cp_commit() {
    asm volatile("cp.async.commit_group;" ::: "memory");
}
template<int N> __device__ __forceinline__ void cp_wait() {
    asm volatile("cp.async.wait_group %0;" :: "n"(N) : "memory");
}
__device__ __forceinline__ void ldsm4(uint32_t* r, uint32_t a) {
    asm volatile("ldmatrix.sync.aligned.m8n8.x4.shared.b16 {%0,%1,%2,%3}, [%4];"
                 : "=r"(r[0]), "=r"(r[1]), "=r"(r[2]), "=r"(r[3]) : "r"(a));
}
__device__ __forceinline__ void mma16816(float* c, const uint32_t* a,
                                         uint32_t b0, uint32_t b1) {
    asm volatile(
        "mma.sync.aligned.m16n8k16.row.col.f32.f16.f16.f32 "
        "{%0,%1,%2,%3}, {%4,%5,%6,%7}, {%8,%9}, {%0,%1,%2,%3};"
        : "+f"(c[0]), "+f"(c[1]), "+f"(c[2]), "+f"(c[3])
        : "r"(a[0]), "r"(a[1]), "r"(a[2]), "r"(a[3]), "r"(b0), "r"(b1));
}

__global__ __launch_bounds__(256, 4) void gemm_mma_kernel(
    const float* __restrict__ bias, float* __restrict__ out)
{
    extern __shared__ char sm[];
    const int tid  = threadIdx.x;
    const int lane = tid & 31;
    const int wid  = tid >> 5;      // 0..7
    const int wm   = wid & 1;       // 0..1: 32-row slab
    const int wn   = wid >> 1;      // 0..3: 32-col slab
    const int bn   = blockIdx.x;    // 0..3
    const int bm   = blockIdx.y;    // 0..255
    const uint32_t sbase = smem_u32(sm);

    auto load_stage = [&](int s, int kt) {
        const int k0 = kt * BK;
        const uint32_t d0 = sbase + s * STG;
        {   // A: 64 rows x 4 float4-chunks, 1/thread
            const int r = tid >> 2, cc = tid & 3;
            cp16(d0 + (uint32_t)(r * RS + cc * 16),
                 g_Af + (size_t)(bm * 64 + r) * D + k0 + cc * 8);
        }
        #pragma unroll
        for (int hh = 0; hh < 2; ++hh) {   // W: 128 rows, 512 chunks, 2/thread
            const int jj = tid + hh * 256;
            const int r = jj >> 2, cc = jj & 3;
            cp16(d0 + MTXA + (uint32_t)(r * RS + cc * 16),
                 g_Wh + (size_t)(bn * 128 + r) * D + k0 + cc * 8);
        }
    };

    const int lrow = lane & 15, lkh = lane >> 4;
    const uint32_t aoff = (uint32_t)((wm * 32 + lrow) * RS + lkh * 16);
    const uint32_t boff = (uint32_t)(MTXA + (wn * 32 + lrow) * RS + lkh * 16);

    float acc[2][4][4] = {};

    #pragma unroll
    for (int p = 0; p < NSTAGE - 1; ++p) { load_stage(p, p); cp_commit(); }

    for (int kt = 0; kt < NK; ++kt) {
        cp_wait<NSTAGE - 2>();
        __syncthreads();

        const uint32_t st0 = sbase + (kt % NSTAGE) * STG;
        #pragma unroll
        for (int st = 0; st < 2; ++st) {
            uint32_t af[2][4], bf[2][4];
            #pragma unroll
            for (int mi = 0; mi < 2; ++mi)
                ldsm4(af[mi], st0 + aoff + mi * (16 * RS) + st * 32);
            #pragma unroll
            for (int nt = 0; nt < 2; ++nt)
                ldsm4(bf[nt], st0 + boff + nt * (16 * RS) + st * 32);
            #pragma unroll
            for (int mi = 0; mi < 2; ++mi)
                #pragma unroll
                for (int nt = 0; nt < 2; ++nt) {
                    mma16816(acc[mi][nt*2+0], af[mi], bf[nt][0], bf[nt][2]);
                    mma16816(acc[mi][nt*2+1], af[mi], bf[nt][1], bf[nt][3]);
                }
        }

        if (kt + NSTAGE - 1 < NK)
            load_stage((kt + NSTAGE - 1) % NSTAGE, kt + NSTAGE - 1);
        cp_commit();
    }

    const int g   = lane >> 2;
    const int tig = lane & 3;
    #pragma unroll
    for (int mi = 0; mi < 2; ++mi) {
        const int row0 = bm * 64 + wm * 32 + mi * 16 + g;
        #pragma unroll
        for (int nt = 0; nt < 2; ++nt)
            #pragma unroll
            for (int nh = 0; nh < 2; ++nh) {
                const float* a4 = acc[mi][nt * 2 + nh];
                const int col = bn * 128 + wn * 32 + nt * 16 + nh * 8 + tig * 2;
                const float2 bv = *(const float2*)(bias + col);
                float2 o0 = { a4[0] + bv.x, a4[1] + bv.y };
                float2 o1 = { a4[2] + bv.x, a4[3] + bv.y };
                *(float2*)(out + (size_t)row0 * D + col)       = o0;
                *(float2*)(out + (size_t)(row0 + 8) * D + col) = o1;
            }
    }
}

// ---------------------------------------------------------------------------
extern "C" void kernel_launch(void* const* d_in, const int* in_sizes, int n_in,
                              void* d_out, int out_size)
{
    const float* q    = (const float*)d_in[0];
    const float* k    = (const float*)d_in[1];
    const float* v    = (const float*)d_in[2];
    // d_in[3] = mask (unused)
    const float* W    = (const float*)d_in[4];
    const float* bias = (const float*)d_in[5];
    float* out = (float*)d_out;

    cudaFuncSetAttribute(gemm_mma_kernel,
                         cudaFuncAttributeMaxDynamicSharedMemorySize, GEMM_DSMEM);

    init_wconv_kernel<<<(D * D) / 1024, 256>>>(W);
    fused_attn_kernel<<<NBLK, 256>>>(q, k, v);
    gemm_mma_kernel<<<dim3(4, 256), 256, GEMM_DSMEM>>>(bias, out);
}